// round 13
// baseline (speedup 1.0000x reference)
#include <cuda_runtime.h>
#include <cuda.h>
#include <cstdint>

// ConsensusAttention: levels [B=8, N=1024, L=6, D=128] fp32.
// Local attention: each token attends to <=13 neighbors (dy^2+dx^2 <= 4 on 32x32 grid),
// self sim fixed at -0.0005, others = (q_i . k_j)/sqrt(D) with k = normalized levels.
//
// Kernel 1: per-row scale = rsqrt(|v|^2) * log2(e)/sqrt(D)  (+ PDL trigger).
// Kernel 2: block = 8x4 token tile; ONE 5D TMA stages the 12x8 halo (49KB) into
// smem with OOB zero-fill. 8 lanes/token -> 62 regs -> 4 blocks/SM (~44% occ).
// Inner loop is pure LDS + packed FFMA2; chunk rotation keeps LDS conflict-free.

#define B_DIM 8
#define N_TOK 1024
#define L_DIM 6
#define D_DIM 128
#define ROWS (B_DIM * N_TOK * L_DIM)   // 49152
#define C_SC 0.12751742119567576f      // (1/sqrt(128)) * log2(e)

#define HALO_ROWS 96                   // 12 (y) x 8 (x)
#define TILE_BYTES  (HALO_ROWS * 512)  // 49152
#define SMEM_TILE_OFF 1024
#define SMEM_TOTAL (SMEM_TILE_OFF + TILE_BYTES)   // 50176

__device__ float g_scale[ROWS];   // rsqrt(|row|^2) * C_SC  (always > 0)

// ---- packed f32x2 helpers ----
__device__ __forceinline__ unsigned long long pk2(float lo, float hi) {
    unsigned long long r;
    asm("mov.b64 %0, {%1, %2};" : "=l"(r) : "f"(lo), "f"(hi));
    return r;
}
__device__ __forceinline__ unsigned long long pk_fma(unsigned long long a,
                                                     unsigned long long b,
                                                     unsigned long long c) {
    unsigned long long d;
    asm("fma.rn.f32x2 %0, %1, %2, %3;" : "=l"(d) : "l"(a), "l"(b), "l"(c));
    return d;
}
__device__ __forceinline__ unsigned long long pk_mul(unsigned long long a,
                                                     unsigned long long b) {
    unsigned long long d;
    asm("mul.rn.f32x2 %0, %1, %2;" : "=l"(d) : "l"(a), "l"(b));
    return d;
}
__device__ __forceinline__ float pk_hadd(unsigned long long a) {
    float lo, hi;
    asm("mov.b64 {%0, %1}, %2;" : "=f"(lo), "=f"(hi) : "l"(a));
    return lo + hi;
}
__device__ __forceinline__ float rsqrt_approx(float x) {
    float r; asm("rsqrt.approx.f32 %0, %1;" : "=f"(r) : "f"(x)); return r;
}
__device__ __forceinline__ float ex2_approx(float x) {
    float r; asm("ex2.approx.f32 %0, %1;" : "=f"(r) : "f"(x)); return r;
}
__device__ __forceinline__ uint32_t smem_u32(const void* p) {
    uint32_t a;
    asm("{ .reg .u64 t; cvta.to.shared.u64 t, %1; cvt.u32.u64 %0, t; }" : "=r"(a) : "l"(p));
    return a;
}
__device__ __forceinline__ ulonglong2 lds128(uint32_t addr) {
    ulonglong2 r;
    asm volatile("ld.shared.v2.u64 {%0, %1}, [%2];" : "=l"(r.x), "=l"(r.y) : "r"(addr));
    return r;
}

// Kernel 1: per-row softmax scale. 8 lanes per row, 4 rows per warp.
__global__ __launch_bounds__(256) void norm_kernel(const float* __restrict__ in) {
    int row  = (blockIdx.x * 256 + threadIdx.x) >> 3;
    int lane = threadIdx.x & 7;
    const float4* p = (const float4*)(in + (size_t)row * D_DIM);
    float4 v0 = p[lane], v1 = p[8 + lane], v2 = p[16 + lane], v3 = p[24 + lane];
    float s = v0.x * v0.x + v0.y * v0.y + v0.z * v0.z + v0.w * v0.w
            + v1.x * v1.x + v1.y * v1.y + v1.z * v1.z + v1.w * v1.w
            + v2.x * v2.x + v2.y * v2.y + v2.z * v2.z + v2.w * v2.w
            + v3.x * v3.x + v3.y * v3.y + v3.z * v3.z + v3.w * v3.w;
    s += __shfl_xor_sync(0xffffffffu, s, 1);
    s += __shfl_xor_sync(0xffffffffu, s, 2);
    s += __shfl_xor_sync(0xffffffffu, s, 4);
    if (lane == 0) g_scale[row] = rsqrt_approx(fmaxf(s, 1e-24f)) * C_SC;
    cudaTriggerProgrammaticLaunchCompletion();
}

// Kernel 2: tile attention. 1536 blocks x 256 threads; thread owns 16 floats
// of one token (8 lanes/token, 4 tokens/warp).
__global__ __launch_bounds__(256, 4) void attn_kernel(
    const __grid_constant__ CUtensorMap tmap,
    float* __restrict__ out)
{
    extern __shared__ char smem[];
    const uint32_t sbase = smem_u32(smem);
    const uint32_t MBAR  = sbase;                 // 8B mbarrier
    float* scales        = (float*)(smem + 16);   // 96 floats
    const uint32_t TILE  = sbase + SMEM_TILE_OFF; // 96 rows x 512B

    const int tid   = threadIdx.x;
    const int bid   = blockIdx.x;
    const int slice = bid >> 5;            // 0..47  (b*6 + l)
    const int tile  = bid & 31;            // 4 (ty) x 8 (tx)
    const int b  = slice / L_DIM;
    const int l  = slice - b * L_DIM;
    const int ty = tile >> 3, tx = tile & 7;
    const int gy0 = ty * 8 - 2, gx0 = tx * 4 - 2;

    if (tid == 0) {
        asm volatile("mbarrier.init.shared.b64 [%0], %1;" :: "r"(MBAR), "r"(1) : "memory");
    }
    __syncthreads();
    if (tid == 0) {
        asm volatile("mbarrier.arrive.expect_tx.shared.b64 _, [%0], %1;"
                     :: "r"(MBAR), "r"((uint32_t)TILE_BYTES) : "memory");
        asm volatile(
            "cp.async.bulk.tensor.5d.shared::cta.global.tile.mbarrier::complete_tx::bytes "
            "[%0], [%1, {%2, %3, %4, %5, %6}], [%7];"
            :: "r"(TILE), "l"(&tmap),
               "r"(0), "r"(gx0), "r"(gy0), "r"(l), "r"(b),
               "r"(MBAR) : "memory");
    }

    // Wait for norm_kernel's g_scale (TMA issue above overlapped with it)
    cudaGridDependencySynchronize();

    // Stage the 96 row scales (0 for off-grid rows)
    if (tid < HALO_ROWS) {
        int ly = tid >> 3, lx = tid & 7;
        int gy = gy0 + ly, gx = gx0 + lx;
        bool ok = ((unsigned)gy < 32u) & ((unsigned)gx < 32u);
        scales[tid] = ok ? g_scale[((b * N_TOK + (gy << 5) + gx) * L_DIM) + l] : 0.0f;
    }
    __syncthreads();

    // Wait for TMA completion
    {
        uint32_t done;
        asm volatile(
            "{\n\t.reg .pred p;\n\t"
            "mbarrier.try_wait.parity.shared.b64 p, [%1], %2;\n\t"
            "selp.b32 %0, 1, 0, p;\n\t}"
            : "=r"(done) : "r"(MBAR), "r"(0u) : "memory");
        if (!done) {
            asm volatile(
                "{\n\t.reg .pred P1;\n\t"
                "W_%=:\n\t"
                "mbarrier.try_wait.parity.shared.b64 P1, [%0], %1;\n\t"
                "@P1 bra.uni D_%=;\n\t"
                "bra.uni W_%=;\n\t"
                "D_%=:\n\t}"
                :: "r"(MBAR), "r"(0u) : "memory");
        }
    }

    // Thread -> token mapping: 8 lanes/token, 4 tokens/warp
    const int t  = tid >> 3;         // token 0..31 within tile
    const int j  = tid & 7;          // lane within token
    const int ly = t >> 2, lx = t & 3;

    // Rotated chunk offsets: lane j owns chunks (8*lx + j + 8i) & 31, i=0..3.
    // A warp's 4 tokens (lx 0..3) x 8 lanes cover all 32 banks each phase.
    uint32_t coff[4];
    #pragma unroll
    for (int i = 0; i < 4; i++)
        coff[i] = (uint32_t)(((8 * lx + j + 8 * i) & 31) * 16);

    // q from self row
    const uint32_t self_ra = TILE + (uint32_t)((((ly + 2) << 3) + (lx + 2)) * 512);
    ulonglong2 q[4];
    #pragma unroll
    for (int i = 0; i < 4; i++) q[i] = lds128(self_ra + coff[i]);

    // Self term: sim = -0.0005 exactly
    const float wself = 0.9995001249791693f;   // exp(-0.0005)
    float ssum = wself;
    const unsigned long long ws2 = pk2(wself, wself);
    ulonglong2 acc[4];
    #pragma unroll
    for (int i = 0; i < 4; i++) {
        acc[i].x = pk_mul(ws2, q[i].x);
        acc[i].y = pk_mul(ws2, q[i].y);
    }

    // 12 non-self neighbors (dy^2+dx^2 <= 4); off-grid rows are zero-filled by
    // TMA and have scale 0 -> w = 0, zero contribution.
    const int dys[12] = {-2, -1, -1, -1,  0,  0, 0, 0, 1, 1, 1, 2};
    const int dxs[12] = { 0, -1,  0,  1, -2, -1, 1, 2,-1, 0, 1, 0};

    #pragma unroll
    for (int n = 0; n < 12; n++) {
        const int srow = ((ly + 2 + dys[n]) << 3) + (lx + 2 + dxs[n]);
        const uint32_t ra = TILE + (uint32_t)(srow * 512);

        ulonglong2 v[4];
        #pragma unroll
        for (int i = 0; i < 4; i++) v[i] = lds128(ra + coff[i]);

        // Two interleaved dp chains, then combine
        unsigned long long dA = pk_mul(q[0].x, v[0].x);
        dA = pk_fma(q[0].y, v[0].y, dA);
        unsigned long long dB = pk_mul(q[1].x, v[1].x);
        dB = pk_fma(q[1].y, v[1].y, dB);
        dA = pk_fma(q[2].x, v[2].x, dA);
        dA = pk_fma(q[2].y, v[2].y, dA);
        dB = pk_fma(q[3].x, v[3].x, dB);
        dB = pk_fma(q[3].y, v[3].y, dB);
        unsigned long long d2;
        asm("add.rn.f32x2 %0, %1, %2;" : "=l"(d2) : "l"(dA), "l"(dB));
        float dp = pk_hadd(d2);

        // 8-lane butterfly (each SHFL serves all 4 tokens in the warp)
        dp += __shfl_xor_sync(0xffffffffu, dp, 1);
        dp += __shfl_xor_sync(0xffffffffu, dp, 2);
        dp += __shfl_xor_sync(0xffffffffu, dp, 4);

        const float sc = scales[srow];
        float w = (sc > 0.0f) ? ex2_approx(dp * sc) : 0.0f;
        ssum += w;
        const unsigned long long w2 = pk2(w, w);
        #pragma unroll
        for (int i = 0; i < 4; i++) {
            acc[i].x = pk_fma(w2, v[i].x, acc[i].x);
            acc[i].y = pk_fma(w2, v[i].y, acc[i].y);
        }
    }

    // Normalize and store (lane's chunks go back to their rotated positions)
    const int gtok = ((ty * 8 + ly) << 5) + (tx * 4 + lx);
    ulonglong2* orow =
        (ulonglong2*)(out + ((size_t)(b * N_TOK + gtok) * L_DIM + l) * D_DIM);
    const float inv = 1.0f / ssum;
    const unsigned long long inv2 = pk2(inv, inv);
    #pragma unroll
    for (int i = 0; i < 4; i++) {
        ulonglong2 o;
        o.x = pk_mul(acc[i].x, inv2);
        o.y = pk_mul(acc[i].y, inv2);
        orow[coff[i] >> 4] = o;
    }
}

extern "C" void kernel_launch(void* const* d_in, const int* in_sizes, int n_in,
                              void* d_out, int out_size) {
    const float* in = (const float*)d_in[0];
    float* out = (float*)d_out;

    typedef CUresult (*EncodeFn)(CUtensorMap*, CUtensorMapDataType, cuuint32_t, void*,
                                 const cuuint64_t*, const cuuint64_t*, const cuuint32_t*,
                                 const cuuint32_t*, CUtensorMapInterleave, CUtensorMapSwizzle,
                                 CUtensorMapL2promotion, CUtensorMapFloatOOBfill);
    EncodeFn encode = nullptr;
    cudaGetDriverEntryPoint("cuTensorMapEncodeTiled", (void**)&encode,
                            cudaEnableDefault, nullptr);

    CUtensorMap tmap;
    cuuint64_t dims[5]    = {128, 32, 32, 6, 8};            // d, gx, gy, l, b
    cuuint64_t strides[4] = {768ull * 4,                    // gx: 3072 B
                             32ull * 768 * 4,               // gy: 98304 B
                             128ull * 4,                    // l:  512 B
                             1024ull * 768 * 4};            // b:  3145728 B
    cuuint32_t box[5] = {128, 8, 12, 1, 1};                 // d, 8 cols, 12 rows
    cuuint32_t es[5]  = {1, 1, 1, 1, 1};
    encode(&tmap, CU_TENSOR_MAP_DATA_TYPE_FLOAT32, 5, (void*)in,
           dims, strides, box, es,
           CU_TENSOR_MAP_INTERLEAVE_NONE, CU_TENSOR_MAP_SWIZZLE_NONE,
           CU_TENSOR_MAP_L2_PROMOTION_L2_128B, CU_TENSOR_MAP_FLOAT_OOB_FILL_NONE);

    cudaFuncSetAttribute(attn_kernel,
                         cudaFuncAttributeMaxDynamicSharedMemorySize, SMEM_TOTAL);

    norm_kernel<<<ROWS / 32, 256>>>(in);   // 1536 blocks

    cudaLaunchConfig_t cfg = {};
    cfg.gridDim  = dim3(1536, 1, 1);       // 48 slices x 32 tiles
    cfg.blockDim = dim3(256, 1, 1);
    cfg.dynamicSmemBytes = SMEM_TOTAL;
    cudaLaunchAttribute attr[1];
    attr[0].id = cudaLaunchAttributeProgrammaticStreamSerialization;
    attr[0].val.programmaticStreamSerializationAllowed = 1;
    cfg.attrs = attr;
    cfg.numAttrs = 1;
    cudaLaunchKernelEx(&cfg, attn_kernel, tmap, out);
}

// round 14
// speedup vs baseline: 1.0352x; 1.0352x over previous
#include <cuda_runtime.h>
#include <cuda.h>
#include <cstdint>

// ConsensusAttention: levels [B=8, N=1024, L=6, D=128] fp32.
// Local attention: each token attends to <=13 neighbors (dy^2+dx^2 <= 4 on 32x32 grid),
// self sim fixed at -0.0005, others = (q_i . k_j)/sqrt(D) with k = normalized levels.
//
// Kernel 1: per-row scale = rsqrt(|v|^2) * log2(e)/sqrt(D)  (+ PDL trigger).
// Kernel 2: block = 8x8 token tile; ONE 5D TMA stages the 12x12 halo (73.7KB)
// into smem with OOB zero-fill. One THREAD owns an adjacent token PAIR (A,B):
// the pair's 18-row neighbor union is loaded once per row and used for both
// tokens' dot products -> 9 rows/token of LDS traffic instead of 13.

#define B_DIM 8
#define N_TOK 1024
#define L_DIM 6
#define D_DIM 128
#define ROWS (B_DIM * N_TOK * L_DIM)   // 49152
#define C_SC 0.12751742119567576f      // (1/sqrt(128)) * log2(e)

#define TILE_BYTES  (144 * 512)        // 12x12 rows x 512B
#define SMEM_TILE_OFF 1024
#define SMEM_TOTAL (SMEM_TILE_OFF + TILE_BYTES)   // 74752

__device__ float g_scale[ROWS];   // rsqrt(|row|^2) * C_SC  (always > 0)

// ---- packed f32x2 helpers ----
__device__ __forceinline__ unsigned long long pk2(float lo, float hi) {
    unsigned long long r;
    asm("mov.b64 %0, {%1, %2};" : "=l"(r) : "f"(lo), "f"(hi));
    return r;
}
__device__ __forceinline__ unsigned long long pk_fma(unsigned long long a,
                                                     unsigned long long b,
                                                     unsigned long long c) {
    unsigned long long d;
    asm("fma.rn.f32x2 %0, %1, %2, %3;" : "=l"(d) : "l"(a), "l"(b), "l"(c));
    return d;
}
__device__ __forceinline__ unsigned long long pk_mul(unsigned long long a,
                                                     unsigned long long b) {
    unsigned long long d;
    asm("mul.rn.f32x2 %0, %1, %2;" : "=l"(d) : "l"(a), "l"(b));
    return d;
}
__device__ __forceinline__ unsigned long long pk_add(unsigned long long a,
                                                     unsigned long long b) {
    unsigned long long d;
    asm("add.rn.f32x2 %0, %1, %2;" : "=l"(d) : "l"(a), "l"(b));
    return d;
}
__device__ __forceinline__ float pk_hadd(unsigned long long a) {
    float lo, hi;
    asm("mov.b64 {%0, %1}, %2;" : "=f"(lo), "=f"(hi) : "l"(a));
    return lo + hi;
}
__device__ __forceinline__ float rsqrt_approx(float x) {
    float r; asm("rsqrt.approx.f32 %0, %1;" : "=f"(r) : "f"(x)); return r;
}
__device__ __forceinline__ float ex2_approx(float x) {
    float r; asm("ex2.approx.f32 %0, %1;" : "=f"(r) : "f"(x)); return r;
}
__device__ __forceinline__ uint32_t smem_u32(const void* p) {
    uint32_t a;
    asm("{ .reg .u64 t; cvta.to.shared.u64 t, %1; cvt.u32.u64 %0, t; }" : "=r"(a) : "l"(p));
    return a;
}
__device__ __forceinline__ ulonglong2 lds128(uint32_t addr) {
    ulonglong2 r;
    asm volatile("ld.shared.v2.u64 {%0, %1}, [%2];" : "=l"(r.x), "=l"(r.y) : "r"(addr));
    return r;
}

// Kernel 1: per-row softmax scale. 8 lanes per row, 4 rows per warp.
__global__ __launch_bounds__(256) void norm_kernel(const float* __restrict__ in) {
    int row  = (blockIdx.x * 256 + threadIdx.x) >> 3;
    int lane = threadIdx.x & 7;
    const float4* p = (const float4*)(in + (size_t)row * D_DIM);
    float4 v0 = p[lane], v1 = p[8 + lane], v2 = p[16 + lane], v3 = p[24 + lane];
    float s = v0.x * v0.x + v0.y * v0.y + v0.z * v0.z + v0.w * v0.w
            + v1.x * v1.x + v1.y * v1.y + v1.z * v1.z + v1.w * v1.w
            + v2.x * v2.x + v2.y * v2.y + v2.z * v2.z + v2.w * v2.w
            + v3.x * v3.x + v3.y * v3.y + v3.z * v3.z + v3.w * v3.w;
    s += __shfl_xor_sync(0xffffffffu, s, 1);
    s += __shfl_xor_sync(0xffffffffu, s, 2);
    s += __shfl_xor_sync(0xffffffffu, s, 4);
    if (lane == 0) g_scale[row] = rsqrt_approx(fmaxf(s, 1e-24f)) * C_SC;
    cudaTriggerProgrammaticLaunchCompletion();
}

// Kernel 2: pair-tile attention. 768 blocks x 256 threads.
// Thread = one horizontal token pair (A at even x, B at x+1); 8 lanes/pair.
__global__ __launch_bounds__(256, 2) void attn_kernel(
    const __grid_constant__ CUtensorMap tmap,
    float* __restrict__ out)
{
    extern __shared__ char smem[];
    const uint32_t sbase = smem_u32(smem);
    const uint32_t MBAR  = sbase;                 // 8B mbarrier
    float* scales        = (float*)(smem + 16);   // 144 floats
    const uint32_t TILE  = sbase + SMEM_TILE_OFF; // 144 rows x 512B

    const int tid   = threadIdx.x;
    const int bid   = blockIdx.x;
    const int slice = bid >> 4;            // 0..47  (b*6 + l)
    const int tile  = bid & 15;
    const int b  = slice / L_DIM;
    const int l  = slice - b * L_DIM;
    const int ty = tile >> 2, tx = tile & 3;
    const int gy0 = ty * 8 - 2, gx0 = tx * 8 - 2;

    if (tid == 0) {
        asm volatile("mbarrier.init.shared.b64 [%0], %1;" :: "r"(MBAR), "r"(1) : "memory");
    }
    __syncthreads();
    if (tid == 0) {
        asm volatile("mbarrier.arrive.expect_tx.shared.b64 _, [%0], %1;"
                     :: "r"(MBAR), "r"((uint32_t)TILE_BYTES) : "memory");
        asm volatile(
            "cp.async.bulk.tensor.5d.shared::cta.global.tile.mbarrier::complete_tx::bytes "
            "[%0], [%1, {%2, %3, %4, %5, %6}], [%7];"
            :: "r"(TILE), "l"(&tmap),
               "r"(0), "r"(gx0), "r"(gy0), "r"(l), "r"(b),
               "r"(MBAR) : "memory");
    }

    // Wait for norm_kernel's g_scale (TMA issue above overlapped with it)
    cudaGridDependencySynchronize();

    // Stage the 144 row scales (0 for off-grid rows)
    if (tid < 144) {
        int sy = tid / 12, sx = tid - sy * 12;
        int gy = gy0 + sy, gx = gx0 + sx;
        bool ok = ((unsigned)gy < 32u) & ((unsigned)gx < 32u);
        scales[tid] = ok ? g_scale[((b * N_TOK + (gy << 5) + gx) * L_DIM) + l] : 0.0f;
    }
    __syncthreads();

    // Wait for TMA completion
    {
        uint32_t done;
        asm volatile(
            "{\n\t.reg .pred p;\n\t"
            "mbarrier.try_wait.parity.shared.b64 p, [%1], %2;\n\t"
            "selp.b32 %0, 1, 0, p;\n\t}"
            : "=r"(done) : "r"(MBAR), "r"(0u) : "memory");
        if (!done) {
            asm volatile(
                "{\n\t.reg .pred P1;\n\t"
                "W_%=:\n\t"
                "mbarrier.try_wait.parity.shared.b64 P1, [%0], %1;\n\t"
                "@P1 bra.uni D_%=;\n\t"
                "bra.uni W_%=;\n\t"
                "D_%=:\n\t}"
                :: "r"(MBAR), "r"(0u) : "memory");
        }
    }

    // Thread -> pair mapping: pair t = tid>>3 (0..31), lane j = tid&7.
    // Pair p: row ly = t>>2 (0..7), pair-col px = t&3 -> A at x'=2*px, B at x'+1.
    const int t  = tid >> 3;
    const int j  = tid & 7;
    const int ly = t >> 2, px = t & 3;
    const int pw = (tid >> 3) & 3;     // pair index within warp (for rotation)

    // Rotated chunk offsets: lane j of warp-pair pw owns chunks (8*pw+j+8i)&31.
    // Each LDS.128 phase (32 lanes, fixed i) covers all 32 distinct 16B banks.
    uint32_t coff[4];
    #pragma unroll
    for (int i = 0; i < 4; i++)
        coff[i] = (uint32_t)(((8 * pw + j + 8 * i) & 31) * 16);

    // Base smem row of A: (ly+2, 2*px+2) in the 12x12 halo
    const int arow = (ly + 2) * 12 + (2 * px + 2);
    const uint32_t abase = TILE + (uint32_t)(arow * 512);

    // q for both tokens
    ulonglong2 qA[4], qB[4];
    #pragma unroll
    for (int i = 0; i < 4; i++) qA[i] = lds128(abase + coff[i]);
    #pragma unroll
    for (int i = 0; i < 4; i++) qB[i] = lds128(abase + 512 + coff[i]);

    // Self terms: sim = -0.0005 exactly
    const float wself = 0.9995001249791693f;   // exp(-0.0005)
    float ssumA = wself, ssumB = wself;
    const unsigned long long ws2 = pk2(wself, wself);
    ulonglong2 accA[4], accB[4];
    #pragma unroll
    for (int i = 0; i < 4; i++) {
        accA[i].x = pk_mul(ws2, qA[i].x);
        accA[i].y = pk_mul(ws2, qA[i].y);
        accB[i].x = pk_mul(ws2, qB[i].x);
        accB[i].y = pk_mul(ws2, qB[i].y);
    }

    // 18-row union of the pair's neighbor disks (relative to A).
    // rA/rB: row is a non-self neighbor of A / of B. Off-grid rows are TMA
    // zero-filled and have scale 0 -> w = 0.
    const int dys[18] = {-2,-2,-1,-1,-1,-1, 0, 0, 0, 0, 0, 0, 1, 1, 1, 1, 2, 2};
    const int dxs[18] = { 0, 1,-1, 0, 1, 2,-2,-1, 0, 1, 2, 3,-1, 0, 1, 2, 0, 1};
    const int rA [18] = { 1, 0, 1, 1, 1, 0, 1, 1, 0, 1, 1, 0, 1, 1, 1, 0, 1, 0};
    const int rB [18] = { 0, 1, 0, 1, 1, 1, 0, 1, 1, 0, 1, 1, 0, 1, 1, 1, 0, 1};

    #pragma unroll
    for (int n = 0; n < 18; n++) {
        const int srow = arow + dys[n] * 12 + dxs[n];
        const uint32_t ra = TILE + (uint32_t)(srow * 512);

        ulonglong2 v[4];
        #pragma unroll
        for (int i = 0; i < 4; i++) v[i] = lds128(ra + coff[i]);

        const float sc = scales[srow];

        float dpA = 0.0f, dpB = 0.0f;
        if (rA[n]) {
            unsigned long long d0 = pk_mul(qA[0].x, v[0].x);
            d0 = pk_fma(qA[0].y, v[0].y, d0);
            unsigned long long d1 = pk_mul(qA[1].x, v[1].x);
            d1 = pk_fma(qA[1].y, v[1].y, d1);
            d0 = pk_fma(qA[2].x, v[2].x, d0);
            d0 = pk_fma(qA[2].y, v[2].y, d0);
            d1 = pk_fma(qA[3].x, v[3].x, d1);
            d1 = pk_fma(qA[3].y, v[3].y, d1);
            dpA = pk_hadd(pk_add(d0, d1));
        }
        if (rB[n]) {
            unsigned long long d0 = pk_mul(qB[0].x, v[0].x);
            d0 = pk_fma(qB[0].y, v[0].y, d0);
            unsigned long long d1 = pk_mul(qB[1].x, v[1].x);
            d1 = pk_fma(qB[1].y, v[1].y, d1);
            d0 = pk_fma(qB[2].x, v[2].x, d0);
            d0 = pk_fma(qB[2].y, v[2].y, d0);
            d1 = pk_fma(qB[3].x, v[3].x, d1);
            d1 = pk_fma(qB[3].y, v[3].y, d1);
            dpB = pk_hadd(pk_add(d0, d1));
        }

        // 8-lane butterfly; each SHFL serves all 4 pairs in the warp.
        #pragma unroll
        for (int m = 1; m < 8; m <<= 1) {
            if (rA[n]) dpA += __shfl_xor_sync(0xffffffffu, dpA, m);
            if (rB[n]) dpB += __shfl_xor_sync(0xffffffffu, dpB, m);
        }

        if (rA[n]) {
            float w = (sc > 0.0f) ? ex2_approx(dpA * sc) : 0.0f;
            ssumA += w;
            const unsigned long long w2 = pk2(w, w);
            #pragma unroll
            for (int i = 0; i < 4; i++) {
                accA[i].x = pk_fma(w2, v[i].x, accA[i].x);
                accA[i].y = pk_fma(w2, v[i].y, accA[i].y);
            }
        }
        if (rB[n]) {
            float w = (sc > 0.0f) ? ex2_approx(dpB * sc) : 0.0f;
            ssumB += w;
            const unsigned long long w2 = pk2(w, w);
            #pragma unroll
            for (int i = 0; i < 4; i++) {
                accB[i].x = pk_fma(w2, v[i].x, accB[i].x);
                accB[i].y = pk_fma(w2, v[i].y, accB[i].y);
            }
        }
    }

    // Normalize and store both tokens
    const int gtokA = ((ty * 8 + ly) << 5) + (tx * 8 + 2 * px);
    ulonglong2* orowA =
        (ulonglong2*)(out + ((size_t)(b * N_TOK + gtokA) * L_DIM + l) * D_DIM);
    ulonglong2* orowB = orowA + (L_DIM * D_DIM / 4);   // next token, +768 floats

    const float invA = 1.0f / ssumA;
    const unsigned long long iA2 = pk2(invA, invA);
    #pragma unroll
    for (int i = 0; i < 4; i++) {
        ulonglong2 o;
        o.x = pk_mul(accA[i].x, iA2);
        o.y = pk_mul(accA[i].y, iA2);
        orowA[coff[i] >> 4] = o;
    }
    const float invB = 1.0f / ssumB;
    const unsigned long long iB2 = pk2(invB, invB);
    #pragma unroll
    for (int i = 0; i < 4; i++) {
        ulonglong2 o;
        o.x = pk_mul(accB[i].x, iB2);
        o.y = pk_mul(accB[i].y, iB2);
        orowB[coff[i] >> 4] = o;
    }
}

extern "C" void kernel_launch(void* const* d_in, const int* in_sizes, int n_in,
                              void* d_out, int out_size) {
    const float* in = (const float*)d_in[0];
    float* out = (float*)d_out;

    typedef CUresult (*EncodeFn)(CUtensorMap*, CUtensorMapDataType, cuuint32_t, void*,
                                 const cuuint64_t*, const cuuint64_t*, const cuuint32_t*,
                                 const cuuint32_t*, CUtensorMapInterleave, CUtensorMapSwizzle,
                                 CUtensorMapL2promotion, CUtensorMapFloatOOBfill);
    EncodeFn encode = nullptr;
    cudaGetDriverEntryPoint("cuTensorMapEncodeTiled", (void**)&encode,
                            cudaEnableDefault, nullptr);

    CUtensorMap tmap;
    cuuint64_t dims[5]    = {128, 32, 32, 6, 8};            // d, gx, gy, l, b
    cuuint64_t strides[4] = {768ull * 4, 32ull * 768 * 4, 128ull * 4, 1024ull * 768 * 4};
    cuuint32_t box[5] = {128, 12, 12, 1, 1};
    cuuint32_t es[5]  = {1, 1, 1, 1, 1};
    encode(&tmap, CU_TENSOR_MAP_DATA_TYPE_FLOAT32, 5, (void*)in,
           dims, strides, box, es,
           CU_TENSOR_MAP_INTERLEAVE_NONE, CU_TENSOR_MAP_SWIZZLE_NONE,
           CU_TENSOR_MAP_L2_PROMOTION_L2_128B, CU_TENSOR_MAP_FLOAT_OOB_FILL_NONE);

    cudaFuncSetAttribute(attn_kernel,
                         cudaFuncAttributeMaxDynamicSharedMemorySize, SMEM_TOTAL);

    norm_kernel<<<ROWS / 32, 256>>>(in);   // 1536 blocks

    cudaLaunchConfig_t cfg = {};
    cfg.gridDim  = dim3(768, 1, 1);        // 48 slices x 16 tiles
    cfg.blockDim = dim3(256, 1, 1);
    cfg.dynamicSmemBytes = SMEM_TOTAL;
    cudaLaunchAttribute attr[1];
    attr[0].id = cudaLaunchAttributeProgrammaticStreamSerialization;
    attr[0].val.programmaticStreamSerializationAllowed = 1;
    cfg.attrs = attr;
    cfg.numAttrs = 1;
    cudaLaunchKernelEx(&cfg, attn_kernel, tmap, out);
}